// round 4
// baseline (speedup 1.0000x reference)
#include <cuda_runtime.h>
#include <cuda_bf16.h>

#define NB 131072
#define D 32
#define H 50
#define KOBS 5

// ---------------- device scratch (no allocations allowed) ----------------
__device__ int            g_count[10];
__device__ int            g_cursor[10];
__device__ int            g_nsteps[10];
__device__ float          g_dts[64];
__device__ unsigned char  g_rmin[NB];
__device__ int            g_perm[NB];

__device__ __forceinline__ float fast_tanh(float x) {
    float y;
    asm("tanh.approx.f32 %0, %1;" : "=f"(y) : "f"(x));
    return y;
}

__device__ __forceinline__ unsigned long long pack2(float a, float b) {
    unsigned long long r;
    asm("mov.b64 %0, {%1, %2};" : "=l"(r) : "f"(a), "f"(b));
    return r;
}
__device__ __forceinline__ void unpack2(unsigned long long v, float& a, float& b) {
    asm("mov.b64 {%0, %1}, %2;" : "=f"(a), "=f"(b) : "l"(v));
}
// d = a*b + d  (packed 2x fp32; PTX ISA 8.6, sm_100a+)
__device__ __forceinline__ void ffma2(unsigned long long& d,
                                      unsigned long long a,
                                      unsigned long long b) {
    asm("fma.rn.f32x2 %0, %1, %2, %0;" : "+l"(d) : "l"(a), "l"(b));
}
// packed add
__device__ __forceinline__ unsigned long long fadd2(unsigned long long a,
                                                    unsigned long long b) {
    unsigned long long r;
    asm("add.rn.f32x2 %0, %1, %2;" : "=l"(r) : "l"(a), "l"(b));
    return r;
}

// ---------------- kernel 1: zero counters ----------------
__global__ void k_init() {
    if (threadIdx.x < 10) g_count[threadIdx.x] = 0;
}

// ---------------- kernel 2: per-row min + histogram ----------------
__global__ void k_meta(const int* __restrict__ t) {
    __shared__ int s_cnt[10];
    int tid = blockIdx.x * blockDim.x + threadIdx.x;
    if (threadIdx.x < 10) s_cnt[threadIdx.x] = 0;
    __syncthreads();
    if (tid < NB) {
        const int* r = t + (size_t)tid * KOBS;
        int v = r[0];
        v = min(v, r[1]);
        v = min(v, r[2]);
        v = min(v, r[3]);
        v = min(v, r[4]);
        g_rmin[tid] = (unsigned char)v;
        atomicAdd(&s_cnt[v], 1);
    }
    __syncthreads();
    if (threadIdx.x < 10 && s_cnt[threadIdx.x] > 0)
        atomicAdd(&g_count[threadIdx.x], s_cnt[threadIdx.x]);
}

// ---------------- kernel 3: build time grid ----------------
// Exact float64 replica of the numpy split_time logic. All scratch lives in
// SHARED memory (dynamically indexed local arrays would grow the device
// local-memory pool and trip the allocation guard).
__global__ void k_grid() {
    __shared__ double res[10];
    __shared__ double ls[48];
    __shared__ double times[64];
    __shared__ int    vres[10];
    if (threadIdx.x != 0) return;

    int nres = 0;
    for (int v = 0; v < 10; v++) {
        if (g_count[v] > 0) {
            res[nres]  = (double)v / 10.0;
            vres[nres] = v;
            nres++;
        }
    }
    double max_time = res[nres - 1];
    if (max_time < 1e-4) max_time = 1e-4;
    double step = (0.1 <= max_time) ? 0.1 : max_time / 20.0;
    int num = (int)(max_time / step);   // trunc toward zero, same as python int()
    if (num > 48) num = 48;

    if (num >= 2) {
        double delta = max_time / (double)(num - 1);
        for (int k = 0; k < num; k++) ls[k] = (double)k * delta;
        ls[num - 1] = max_time;   // numpy linspace endpoint is exact
    } else if (num == 1) {
        ls[0] = 0.0;
    }

    // merge-unique two sorted lists (exact fp64 equality, same as np.unique)
    int T = 0, i = 0, j = 0;
    while (i < nres || j < num) {
        double a = (i < nres) ? res[i] : 1e300;
        double b = (j < num)  ? ls[j]  : 1e300;
        double x;
        if (a < b)      { x = a; i++; }
        else if (b < a) { x = b; j++; }
        else            { x = a; i++; j++; }
        if (T == 0 || x != times[T - 1]) times[T++] = x;
    }

    for (int q = 0; q < T - 1; q++) g_dts[q] = (float)(times[q + 1] - times[q]);
    for (int q = T - 1; q < 64; q++) g_dts[q] = 0.0f;

    for (int v = 0; v < 10; v++) g_nsteps[v] = 0;
    for (int s = 0; s < nres; s++) {
        double val = res[s];
        for (int q = 0; q < T; q++) {
            if (times[q] == val) { g_nsteps[vres[s]] = q; break; }
        }
    }

    // exclusive prefix sum -> bucket cursors
    int off = 0;
    for (int v = 0; v < 10; v++) {
        g_cursor[v] = off;
        off += g_count[v];
    }
}

// ---------------- kernel 4: bucket rows by step count ----------------
__global__ void k_bucket() {
    __shared__ int s_cnt[10], s_base[10];
    int tid = blockIdx.x * blockDim.x + threadIdx.x;
    if (threadIdx.x < 10) s_cnt[threadIdx.x] = 0;
    __syncthreads();
    int v = 0, my = 0;
    bool act = (tid < NB);
    if (act) {
        v  = g_rmin[tid];
        my = atomicAdd(&s_cnt[v], 1);
    }
    __syncthreads();
    if (threadIdx.x < 10)
        s_base[threadIdx.x] = atomicAdd(&g_cursor[threadIdx.x], s_cnt[threadIdx.x]);
    __syncthreads();
    if (act) g_perm[s_base[v] + my] = tid;
}

// ---------------- kernel 5: main integration ----------------
// Per-thread live state ~114 floats: y[32] + h1 (25 packed pairs) + acc3 (16
// packed pairs). Layers 2+3 fused: each h2[j] is computed with 5 independent
// partial accumulators (breaks the serial FMA chain; 5-way ILP) and consumed
// immediately into the acc3 scatter. All math uses packed fma.rn.f32x2.
__global__ void __launch_bounds__(128) k_main(
    const float* __restrict__ x,
    const float* __restrict__ W1, const float* __restrict__ b1,
    const float* __restrict__ W2, const float* __restrict__ b2,
    const float* __restrict__ W3, const float* __restrict__ b3,
    float* __restrict__ out)
{
    __shared__ __align__(16) float sW1[D * H];    // [32][50] row-major
    __shared__ __align__(16) float sW2T[H * H];   // [j][i] = W2[i][j]
    __shared__ __align__(16) float sW3[H * D];    // [50][32] row-major
    __shared__ float sb1[H], sb2[H], sb3[D], sdt[64];

    for (int i = threadIdx.x; i < D * H; i += blockDim.x) sW1[i] = W1[i];
    for (int i = threadIdx.x; i < H * H; i += blockDim.x) {
        int r = i / H, c = i % H;
        sW2T[c * H + r] = W2[i];
    }
    for (int i = threadIdx.x; i < H * D; i += blockDim.x) sW3[i] = W3[i];
    if (threadIdx.x < H)  sb1[threadIdx.x] = b1[threadIdx.x];
    if (threadIdx.x < H)  sb2[threadIdx.x] = b2[threadIdx.x];
    if (threadIdx.x < D)  sb3[threadIdx.x] = b3[threadIdx.x];
    if (threadIdx.x < 64) sdt[threadIdx.x] = g_dts[threadIdx.x];
    __syncthreads();

    int tid = blockIdx.x * blockDim.x + threadIdx.x;
    if (tid >= NB) return;

    int b = g_perm[tid];
    int n = g_nsteps[g_rmin[b]];

    float y[D];
    const float4* xr = (const float4*)(x + (size_t)b * D);
    #pragma unroll
    for (int q = 0; q < D / 4; q++) {
        float4 t = xr[q];
        y[4 * q + 0] = t.x;
        y[4 * q + 1] = t.y;
        y[4 * q + 2] = t.z;
        y[4 * q + 3] = t.w;
    }

    for (int s = 0; s < n; s++) {
        float dt = sdt[s];

        // ---- layer 1: h1 = tanh(y @ W1 + b1), 25 independent pair-accums ----
        unsigned long long acc1[H / 2];
        #pragma unroll
        for (int p = 0; p < H / 2; p++)
            acc1[p] = pack2(sb1[2 * p], sb1[2 * p + 1]);
        #pragma unroll
        for (int i = 0; i < D; i++) {
            unsigned long long yd = pack2(y[i], y[i]);
            const unsigned long long* w =
                (const unsigned long long*)(sW1 + i * H);
            #pragma unroll
            for (int p = 0; p < H / 2; p++) ffma2(acc1[p], yd, w[p]);
        }
        #pragma unroll
        for (int p = 0; p < H / 2; p++) {
            float a0, a1;
            unpack2(acc1[p], a0, a1);
            acc1[p] = pack2(fast_tanh(a0), fast_tanh(a1));   // now h1 pairs
        }

        // ---- fused layers 2+3 ----
        unsigned long long acc3[D / 2];
        #pragma unroll
        for (int p = 0; p < D / 2; p++)
            acc3[p] = pack2(sb3[2 * p], sb3[2 * p + 1]);

        #pragma unroll 1        // rolled: register-array indices don't depend on j
        for (int j = 0; j < H; j++) {
            // dot(h1, W2T[j]) with 5 independent partial accumulators
            const unsigned long long* w2 =
                (const unsigned long long*)(sW2T + j * H);
            unsigned long long pa0 = pack2(sb2[j], 0.0f);
            unsigned long long pa1 = pack2(0.0f, 0.0f);
            unsigned long long pa2 = pa1, pa3 = pa1, pa4 = pa1;
            #pragma unroll
            for (int p = 0; p < 5; p++) {
                ffma2(pa0, acc1[5 * p + 0], w2[5 * p + 0]);
                ffma2(pa1, acc1[5 * p + 1], w2[5 * p + 1]);
                ffma2(pa2, acc1[5 * p + 2], w2[5 * p + 2]);
                ffma2(pa3, acc1[5 * p + 3], w2[5 * p + 3]);
                ffma2(pa4, acc1[5 * p + 4], w2[5 * p + 4]);
            }
            unsigned long long t01 = fadd2(pa0, pa1);
            unsigned long long t23 = fadd2(pa2, pa3);
            unsigned long long tt  = fadd2(fadd2(t01, t23), pa4);
            float a0, a1;
            unpack2(tt, a0, a1);
            float h2j = fast_tanh(a0 + a1);

            unsigned long long hd = pack2(h2j, h2j);
            const unsigned long long* w3 =
                (const unsigned long long*)(sW3 + j * D);
            #pragma unroll
            for (int p = 0; p < D / 2; p++) ffma2(acc3[p], hd, w3[p]);
        }

        // ---- y += dt * tanh(acc3) ----
        #pragma unroll
        for (int p = 0; p < D / 2; p++) {
            float a0, a1;
            unpack2(acc3[p], a0, a1);
            y[2 * p + 0] = fmaf(dt, fast_tanh(a0), y[2 * p + 0]);
            y[2 * p + 1] = fmaf(dt, fast_tanh(a1), y[2 * p + 1]);
        }
    }

    float4* orow = (float4*)(out + (size_t)b * D);
    #pragma unroll
    for (int q = 0; q < D / 4; q++) {
        float4 t;
        t.x = y[4 * q + 0];
        t.y = y[4 * q + 1];
        t.z = y[4 * q + 2];
        t.w = y[4 * q + 3];
        orow[q] = t;
    }
}

// ---------------- launch ----------------
extern "C" void kernel_launch(void* const* d_in, const int* in_sizes, int n_in,
                              void* d_out, int out_size)
{
    const float* x  = (const float*)d_in[0];
    const int*   ti = (const int*)  d_in[1];
    const float* W1 = (const float*)d_in[2];
    const float* b1 = (const float*)d_in[3];
    const float* W2 = (const float*)d_in[4];
    const float* b2 = (const float*)d_in[5];
    const float* W3 = (const float*)d_in[6];
    const float* b3 = (const float*)d_in[7];
    float* out = (float*)d_out;

    k_init<<<1, 32>>>();
    k_meta<<<(NB + 255) / 256, 256>>>(ti);
    k_grid<<<1, 32>>>();
    k_bucket<<<(NB + 255) / 256, 256>>>();
    k_main<<<NB / 128, 128>>>(x, W1, b1, W2, b2, W3, b3, out);
}